// round 8
// baseline (speedup 1.0000x reference)
#include <cuda_runtime.h>
#include <cuda_bf16.h>
#include <cstdint>

// SVD_Solver: batched weighted Kabsch via Horn quaternion method.
// points (B,M,3) f32, weight (B,M,J) f32, offset (B,M,J,3) f32.
// out = [R (B,J,3,3) ; t (B,J,3)], f32.
//
// R8: two-kernel split.
//  Kernel A (reduce): R7's cp.async staging + reduction; writes 22 sums per
//    (b,j) to __device__ scratch (coalesced via smem transpose). No solve
//    tail -> every CTA slot issues memory -> higher achieved HBM BW.
//  Kernel B (solve): one Horn solve per thread, 98304 threads dense.

#define B_N 4096
#define M_N 64
#define J_N 24

#define O_HALF (32 * J_N * 3)       // 2304 floats = 9216 B per half
#define Q_FLOATS (M_N * 3)          // 192
#define SUM_STRIDE 23               // 22 sums + pad, gcd(23,32)=1
#define NSUM 22
#define BSUM (NSUM * J_N)           // 528 floats per batch in scratch

__device__ float g_sums[(size_t)B_N * BSUM];   // 8.65 MB scratch

__device__ __forceinline__ void cp_async16(uint32_t smem_addr, const void* gptr) {
    asm volatile("cp.async.cg.shared.global [%0], [%1], 16;\n"
                 :: "r"(smem_addr), "l"(gptr));
}
__device__ __forceinline__ void cp_commit() {
    asm volatile("cp.async.commit_group;\n");
}
template <int N>
__device__ __forceinline__ void cp_wait() {
    asm volatile("cp.async.wait_group %0;\n" :: "n"(N));
}

// ---------------- Kernel A: staged reduction ----------------
__global__ void __launch_bounds__(128, 10)
svd_reduce_kernel(const float* __restrict__ points,
                  const float* __restrict__ weight,
                  const float* __restrict__ offset)
{
    __shared__ __align__(16) float smo[2 * O_HALF];
    __shared__ __align__(16) float smq[Q_FLOATS];
    __shared__ float sums[J_N * SUM_STRIDE];

    const int tid = threadIdx.x;
    const int b = blockIdx.x;

    const float* go = offset + (size_t)b * (M_N * J_N * 3);
    const float* gw = weight + (size_t)b * (M_N * J_N);
    const float* gq = points + (size_t)b * Q_FLOATS;

    {
        const uint32_t so = (uint32_t)__cvta_generic_to_shared(smo);
        const uint32_t sq = (uint32_t)__cvta_generic_to_shared(smq);
#pragma unroll
        for (int k = 0; k < 5; ++k) {
            int idx = k * 128 + tid;
            if (idx < O_HALF / 4)
                cp_async16(so + idx * 16, go + idx * 4);
        }
        if (tid < Q_FLOATS / 4)
            cp_async16(sq + tid * 16, gq + tid * 4);
        cp_commit();                                   // group A: half0 + points
#pragma unroll
        for (int k = 0; k < 5; ++k) {
            int idx = k * 128 + tid;
            if (idx < O_HALF / 4)
                cp_async16(so + O_HALF * 4 + idx * 16, go + O_HALF + idx * 4);
        }
        cp_commit();                                   // group B: half1
    }

    const int j = tid >> 2;
    const int sub = tid & 3;

    float sw = 0.f;
    float sP0 = 0.f, sP1 = 0.f, sP2 = 0.f;
    float sQ0 = 0.f, sQ1 = 0.f, sQ2 = 0.f;
    float wP0 = 0.f, wP1 = 0.f, wP2 = 0.f;
    float wQ0 = 0.f, wQ1 = 0.f, wQ2 = 0.f;
    float s00 = 0.f, s01 = 0.f, s02 = 0.f;
    float s10 = 0.f, s11 = 0.f, s12 = 0.f;
    float s20 = 0.f, s21 = 0.f, s22 = 0.f;

#pragma unroll 1
    for (int half = 0; half < 2; ++half) {
        if (half == 0) cp_wait<1>(); else cp_wait<0>();
        __syncthreads();

        if (tid < 96) {
            const int mbase = half * 32;
            const float* ob = smo + half * O_HALF;

            float wreg[8];
#pragma unroll
            for (int ml = 0; ml < 8; ++ml)
                wreg[ml] = gw[(mbase + ml * 4 + sub) * J_N + j];

#pragma unroll
            for (int ml = 0; ml < 8; ++ml) {
                const int m_local = ml * 4 + sub;
                const float* po = ob + (m_local * J_N + j) * 3;
                float p0 = po[0], p1 = po[1], p2 = po[2];
                const float* pq = smq + (mbase + m_local) * 3;
                float q0 = pq[0], q1 = pq[1], q2 = pq[2];
                float w = wreg[ml];

                sw += w;
                sP0 += p0; sP1 += p1; sP2 += p2;
                sQ0 += q0; sQ1 += q1; sQ2 += q2;
                wP0 = fmaf(w, p0, wP0); wP1 = fmaf(w, p1, wP1); wP2 = fmaf(w, p2, wP2);
                wQ0 = fmaf(w, q0, wQ0); wQ1 = fmaf(w, q1, wQ1); wQ2 = fmaf(w, q2, wQ2);
                s00 = fmaf(p0, q0, s00); s01 = fmaf(p0, q1, s01); s02 = fmaf(p0, q2, s02);
                s10 = fmaf(p1, q0, s10); s11 = fmaf(p1, q1, s11); s12 = fmaf(p1, q2, s12);
                s20 = fmaf(p2, q0, s20); s21 = fmaf(p2, q1, s21); s22 = fmaf(p2, q2, s22);
            }
        }
    }

    if (tid < 96) {
#pragma unroll
        for (int d = 1; d < 4; d <<= 1) {
            sw  += __shfl_xor_sync(0xffffffffu, sw,  d);
            sP0 += __shfl_xor_sync(0xffffffffu, sP0, d);
            sP1 += __shfl_xor_sync(0xffffffffu, sP1, d);
            sP2 += __shfl_xor_sync(0xffffffffu, sP2, d);
            sQ0 += __shfl_xor_sync(0xffffffffu, sQ0, d);
            sQ1 += __shfl_xor_sync(0xffffffffu, sQ1, d);
            sQ2 += __shfl_xor_sync(0xffffffffu, sQ2, d);
            wP0 += __shfl_xor_sync(0xffffffffu, wP0, d);
            wP1 += __shfl_xor_sync(0xffffffffu, wP1, d);
            wP2 += __shfl_xor_sync(0xffffffffu, wP2, d);
            wQ0 += __shfl_xor_sync(0xffffffffu, wQ0, d);
            wQ1 += __shfl_xor_sync(0xffffffffu, wQ1, d);
            wQ2 += __shfl_xor_sync(0xffffffffu, wQ2, d);
            s00 += __shfl_xor_sync(0xffffffffu, s00, d);
            s01 += __shfl_xor_sync(0xffffffffu, s01, d);
            s02 += __shfl_xor_sync(0xffffffffu, s02, d);
            s10 += __shfl_xor_sync(0xffffffffu, s10, d);
            s11 += __shfl_xor_sync(0xffffffffu, s11, d);
            s12 += __shfl_xor_sync(0xffffffffu, s12, d);
            s20 += __shfl_xor_sync(0xffffffffu, s20, d);
            s21 += __shfl_xor_sync(0xffffffffu, s21, d);
            s22 += __shfl_xor_sync(0xffffffffu, s22, d);
        }
        if (sub == 0) {
            float* s = sums + j * SUM_STRIDE;
            s[0]  = sw;
            s[1]  = sP0; s[2]  = sP1; s[3]  = sP2;
            s[4]  = sQ0; s[5]  = sQ1; s[6]  = sQ2;
            s[7]  = wP0; s[8]  = wP1; s[9]  = wP2;
            s[10] = wQ0; s[11] = wQ1; s[12] = wQ2;
            s[13] = s00; s[14] = s01; s[15] = s02;
            s[16] = s10; s[17] = s11; s[18] = s12;
            s[19] = s20; s[20] = s21; s[21] = s22;
        }
    }
    __syncthreads();

    // Transposed coalesced store: scratch[b][k*24 + j] = sums[j][k]
    float* dst = g_sums + (size_t)b * BSUM;
#pragma unroll
    for (int base = 0; base < BSUM; base += 128) {
        int idx = base + tid;
        if (idx < BSUM) {
            int k = idx / J_N;
            int jj = idx - k * J_N;
            dst[idx] = sums[jj * SUM_STRIDE + k];
        }
    }
}

// ---------------- Kernel B: dense Horn solve ----------------
__global__ void __launch_bounds__(128)
svd_solve_kernel(float* __restrict__ out)
{
    const int grp = blockIdx.x * 128 + threadIdx.x;   // 0..98303 (exact)
    const int b = grp / J_N;
    const int j = grp - b * J_N;

    const float* s = g_sums + (size_t)b * BSUM + j;   // element k at s[k*24]
#define SV(k) s[(k) * J_N]
    float Tsw  = SV(0);
    float TsP0 = SV(1),  TsP1 = SV(2),  TsP2 = SV(3);
    float TsQ0 = SV(4),  TsQ1 = SV(5),  TsQ2 = SV(6);
    float TwP0 = SV(7),  TwP1 = SV(8),  TwP2 = SV(9);
    float TwQ0 = SV(10), TwQ1 = SV(11), TwQ2 = SV(12);
    float t00 = SV(13), t01 = SV(14), t02 = SV(15);
    float t10 = SV(16), t11 = SV(17), t12 = SV(18);
    float t20 = SV(19), t21 = SV(20), t22 = SV(21);
#undef SV

    float inv = 1.0f / Tsw;
    float Pb0 = TwP0 * inv, Pb1 = TwP1 * inv, Pb2 = TwP2 * inv;
    float Qb0 = TwQ0 * inv, Qb1 = TwQ1 * inv, Qb2 = TwQ2 * inv;

    float g0 = TsP0 - (float)M_N * Pb0;
    float g1 = TsP1 - (float)M_N * Pb1;
    float g2 = TsP2 - (float)M_N * Pb2;

    float Sxx = t00 - Pb0 * TsQ0 - g0 * Qb0;
    float Sxy = t01 - Pb0 * TsQ1 - g0 * Qb1;
    float Sxz = t02 - Pb0 * TsQ2 - g0 * Qb2;
    float Syx = t10 - Pb1 * TsQ0 - g1 * Qb0;
    float Syy = t11 - Pb1 * TsQ1 - g1 * Qb1;
    float Syz = t12 - Pb1 * TsQ2 - g1 * Qb2;
    float Szx = t20 - Pb2 * TsQ0 - g2 * Qb0;
    float Szy = t21 - Pb2 * TsQ1 - g2 * Qb1;
    float Szz = t22 - Pb2 * TsQ2 - g2 * Qb2;

    float n00 = Sxx + Syy + Szz;
    float n01 = Syz - Szy;
    float n02 = Szx - Sxz;
    float n03 = Sxy - Syx;
    float n11 = Sxx - Syy - Szz;
    float n12 = Sxy + Syx;
    float n13 = Szx + Sxz;
    float n22 = -Sxx + Syy - Szz;
    float n23 = Syz + Szy;
    float n33 = -Sxx - Syy + Szz;

    float f2 = n00 * n00 + n11 * n11 + n22 * n22 + n33 * n33 +
               2.0f * (n01 * n01 + n02 * n02 + n03 * n03 +
                       n12 * n12 + n13 * n13 + n23 * n23);
    float sh = sqrtf(f2) + 1e-30f;

    float b00 = n00 + sh, b01 = n01, b02 = n02, b03 = n03;
    float b11 = n11 + sh, b12 = n12, b13 = n13;
    float b22 = n22 + sh, b23 = n23;
    float b33 = n33 + sh;

#pragma unroll 1
    for (int it = 0; it < 16; ++it) {
        float c00 = b00 * b00 + b01 * b01 + b02 * b02 + b03 * b03;
        float c01 = b00 * b01 + b01 * b11 + b02 * b12 + b03 * b13;
        float c02 = b00 * b02 + b01 * b12 + b02 * b22 + b03 * b23;
        float c03 = b00 * b03 + b01 * b13 + b02 * b23 + b03 * b33;
        float c11 = b01 * b01 + b11 * b11 + b12 * b12 + b13 * b13;
        float c12 = b01 * b02 + b11 * b12 + b12 * b22 + b13 * b23;
        float c13 = b01 * b03 + b11 * b13 + b12 * b23 + b13 * b33;
        float c22 = b02 * b02 + b12 * b12 + b22 * b22 + b23 * b23;
        float c23 = b02 * b03 + b12 * b13 + b22 * b23 + b23 * b33;
        float c33 = b03 * b03 + b13 * b13 + b23 * b23 + b33 * b33;
        float tr = c00 + c11 + c22 + c33;
        float sc = __frcp_rn(tr);
        b00 = c00 * sc; b01 = c01 * sc; b02 = c02 * sc; b03 = c03 * sc;
        b11 = c11 * sc; b12 = c12 * sc; b13 = c13 * sc;
        b22 = c22 * sc; b23 = c23 * sc;
        b33 = c33 * sc;
    }

    float q0, q1, q2, q3;
    if (b00 >= b11 && b00 >= b22 && b00 >= b33) {
        q0 = b00; q1 = b01; q2 = b02; q3 = b03;
    } else if (b11 >= b22 && b11 >= b33) {
        q0 = b01; q1 = b11; q2 = b12; q3 = b13;
    } else if (b22 >= b33) {
        q0 = b02; q1 = b12; q2 = b22; q3 = b23;
    } else {
        q0 = b03; q1 = b13; q2 = b23; q3 = b33;
    }
    float nq = rsqrtf(q0 * q0 + q1 * q1 + q2 * q2 + q3 * q3);
    q0 *= nq; q1 *= nq; q2 *= nq; q3 *= nq;

    float xx = q1 * q1, yy = q2 * q2, zz = q3 * q3;
    float xy = q1 * q2, xz = q1 * q3, yz = q2 * q3;
    float wx = q0 * q1, wy = q0 * q2, wz = q0 * q3;

    float R00 = 1.0f - 2.0f * (yy + zz);
    float R01 = 2.0f * (xy - wz);
    float R02 = 2.0f * (xz + wy);
    float R10 = 2.0f * (xy + wz);
    float R11 = 1.0f - 2.0f * (xx + zz);
    float R12 = 2.0f * (yz - wx);
    float R20 = 2.0f * (xz - wy);
    float R21 = 2.0f * (yz + wx);
    float R22 = 1.0f - 2.0f * (xx + yy);

    float tx = Qb0 - (R00 * Pb0 + R01 * Pb1 + R02 * Pb2);
    float ty = Qb1 - (R10 * Pb0 + R11 * Pb1 + R12 * Pb2);
    float tz = Qb2 - (R20 * Pb0 + R21 * Pb1 + R22 * Pb2);

    float* oR = out + (size_t)grp * 9;
    oR[0] = R00; oR[1] = R01; oR[2] = R02;
    oR[3] = R10; oR[4] = R11; oR[5] = R12;
    oR[6] = R20; oR[7] = R21; oR[8] = R22;

    float* oT = out + (size_t)B_N * J_N * 9 + (size_t)grp * 3;
    oT[0] = tx; oT[1] = ty; oT[2] = tz;
}

extern "C" void kernel_launch(void* const* d_in, const int* in_sizes, int n_in,
                              void* d_out, int out_size)
{
    const float* points = (const float*)d_in[0];
    const float* weight = (const float*)d_in[1];
    const float* offset = (const float*)d_in[2];
    float* out = (float*)d_out;

    svd_reduce_kernel<<<B_N, 128>>>(points, weight, offset);
    svd_solve_kernel<<<(B_N * J_N) / 128, 128>>>(out);
}

// round 9
// speedup vs baseline: 1.2965x; 1.2965x over previous
#include <cuda_runtime.h>
#include <cuda_bf16.h>
#include <cstdint>

// SVD_Solver: batched weighted Kabsch via Horn quaternion method.
// points (B,M,3) f32, weight (B,M,J) f32, offset (B,M,J,3) f32.
// out = [R (B,J,3,3) ; t (B,J,3)], f32.
//
// R9: fused kernel (R7 structure) + multi-batch pipeline. Each block does
// NB=4 batches; half-buffers are reused so the next batch's cp.async groups
// are issued as soon as the current half is consumed. The single-warp Horn
// solve tail of batch i overlaps the in-flight DMA of batch i+1.

#define B_N 4096
#define M_N 64
#define J_N 24
#define NB  4
#define GRID (B_N / NB)             // 1024

#define O_HALF (32 * J_N * 3)       // 2304 floats = 9216 B per half
#define Q_FLOATS (M_N * 3)          // 192
#define SUM_STRIDE 23               // 22 sums + pad, gcd(23,32)=1

__device__ __forceinline__ void cp_async16(uint32_t smem_addr, const void* gptr) {
    asm volatile("cp.async.cg.shared.global [%0], [%1], 16;\n"
                 :: "r"(smem_addr), "l"(gptr));
}
__device__ __forceinline__ void cp_commit() {
    asm volatile("cp.async.commit_group;\n");
}
template <int N>
__device__ __forceinline__ void cp_wait() {
    asm volatile("cp.async.wait_group %0;\n" :: "n"(N));
}

__global__ void __launch_bounds__(128)
svd_solver_kernel(const float* __restrict__ points,
                  const float* __restrict__ weight,
                  const float* __restrict__ offset,
                  float* __restrict__ out)
{
    __shared__ __align__(16) float smo[2 * O_HALF];     // half0 / half1 slots
    __shared__ __align__(16) float smq[2 * Q_FLOATS];   // points, double buffer
    __shared__ float sums[J_N * SUM_STRIDE];

    const int tid = threadIdx.x;
    const int b0 = blockIdx.x * NB;

    const uint32_t so = (uint32_t)__cvta_generic_to_shared(smo);
    const uint32_t sq = (uint32_t)__cvta_generic_to_shared(smq);

    // Issue half0(+points) of batch i into slot 0 / q-buffer (i&1).
    auto issue_h0 = [&](int i) {
        const float* go = offset + (size_t)(b0 + i) * (M_N * J_N * 3);
        const float* gq = points + (size_t)(b0 + i) * Q_FLOATS;
#pragma unroll
        for (int k = 0; k < 5; ++k) {
            int idx = k * 128 + tid;
            if (idx < O_HALF / 4)
                cp_async16(so + idx * 16, go + idx * 4);
        }
        if (tid < Q_FLOATS / 4)
            cp_async16(sq + (i & 1) * (Q_FLOATS * 4) + tid * 16, gq + tid * 4);
        cp_commit();
    };
    // Issue half1 of batch i into slot 1.
    auto issue_h1 = [&](int i) {
        const float* go = offset + (size_t)(b0 + i) * (M_N * J_N * 3);
#pragma unroll
        for (int k = 0; k < 5; ++k) {
            int idx = k * 128 + tid;
            if (idx < O_HALF / 4)
                cp_async16(so + O_HALF * 4 + idx * 16, go + O_HALF + idx * 4);
        }
        cp_commit();
    };

    issue_h0(0);
    issue_h1(0);

    const int j = tid >> 2;          // valid when tid < 96
    const int sub = tid & 3;

#pragma unroll 1
    for (int i = 0; i < NB; ++i) {
        const float* gw = weight + (size_t)(b0 + i) * (M_N * J_N);
        const float* qb = smq + (i & 1) * Q_FLOATS;

        float sw = 0.f;
        float sP0 = 0.f, sP1 = 0.f, sP2 = 0.f;
        float sQ0 = 0.f, sQ1 = 0.f, sQ2 = 0.f;
        float wP0 = 0.f, wP1 = 0.f, wP2 = 0.f;
        float wQ0 = 0.f, wQ1 = 0.f, wQ2 = 0.f;
        float s00 = 0.f, s01 = 0.f, s02 = 0.f;
        float s10 = 0.f, s11 = 0.f, s12 = 0.f;
        float s20 = 0.f, s21 = 0.f, s22 = 0.f;

#pragma unroll 1
        for (int half = 0; half < 2; ++half) {
            // Wait for this half's group. Pending FIFO:
            //  half0: [h0(i), h1(i)]            -> wait<1>
            //  half1: [h1(i), h0(i+1)] or [h1(i)] -> wait<1> / wait<0>
            if (half == 0) cp_wait<1>();
            else if (i + 1 < NB) cp_wait<1>();
            else cp_wait<0>();
            __syncthreads();

            if (tid < 96) {
                const int mbase = half * 32;
                const float* ob = smo + half * O_HALF;

                float wreg[8];
#pragma unroll
                for (int ml = 0; ml < 8; ++ml)
                    wreg[ml] = gw[(mbase + ml * 4 + sub) * J_N + j];

#pragma unroll
                for (int ml = 0; ml < 8; ++ml) {
                    const int m_local = ml * 4 + sub;
                    const float* po = ob + (m_local * J_N + j) * 3;
                    float p0 = po[0], p1 = po[1], p2 = po[2];
                    const float* pq = qb + (mbase + m_local) * 3;
                    float q0 = pq[0], q1 = pq[1], q2 = pq[2];
                    float w = wreg[ml];

                    sw += w;
                    sP0 += p0; sP1 += p1; sP2 += p2;
                    sQ0 += q0; sQ1 += q1; sQ2 += q2;
                    wP0 = fmaf(w, p0, wP0); wP1 = fmaf(w, p1, wP1); wP2 = fmaf(w, p2, wP2);
                    wQ0 = fmaf(w, q0, wQ0); wQ1 = fmaf(w, q1, wQ1); wQ2 = fmaf(w, q2, wQ2);
                    s00 = fmaf(p0, q0, s00); s01 = fmaf(p0, q1, s01); s02 = fmaf(p0, q2, s02);
                    s10 = fmaf(p1, q0, s10); s11 = fmaf(p1, q1, s11); s12 = fmaf(p1, q2, s12);
                    s20 = fmaf(p2, q0, s20); s21 = fmaf(p2, q1, s21); s22 = fmaf(p2, q2, s22);
                }
            }
            __syncthreads();   // all warps done reading this half's slot

            // Refill the just-freed slot with the next batch's same half.
            if (i + 1 < NB) {
                if (half == 0) issue_h0(i + 1);
                else           issue_h1(i + 1);
            }
        }

        if (tid < 96) {
#pragma unroll
            for (int d = 1; d < 4; d <<= 1) {
                sw  += __shfl_xor_sync(0xffffffffu, sw,  d);
                sP0 += __shfl_xor_sync(0xffffffffu, sP0, d);
                sP1 += __shfl_xor_sync(0xffffffffu, sP1, d);
                sP2 += __shfl_xor_sync(0xffffffffu, sP2, d);
                sQ0 += __shfl_xor_sync(0xffffffffu, sQ0, d);
                sQ1 += __shfl_xor_sync(0xffffffffu, sQ1, d);
                sQ2 += __shfl_xor_sync(0xffffffffu, sQ2, d);
                wP0 += __shfl_xor_sync(0xffffffffu, wP0, d);
                wP1 += __shfl_xor_sync(0xffffffffu, wP1, d);
                wP2 += __shfl_xor_sync(0xffffffffu, wP2, d);
                wQ0 += __shfl_xor_sync(0xffffffffu, wQ0, d);
                wQ1 += __shfl_xor_sync(0xffffffffu, wQ1, d);
                wQ2 += __shfl_xor_sync(0xffffffffu, wQ2, d);
                s00 += __shfl_xor_sync(0xffffffffu, s00, d);
                s01 += __shfl_xor_sync(0xffffffffu, s01, d);
                s02 += __shfl_xor_sync(0xffffffffu, s02, d);
                s10 += __shfl_xor_sync(0xffffffffu, s10, d);
                s11 += __shfl_xor_sync(0xffffffffu, s11, d);
                s12 += __shfl_xor_sync(0xffffffffu, s12, d);
                s20 += __shfl_xor_sync(0xffffffffu, s20, d);
                s21 += __shfl_xor_sync(0xffffffffu, s21, d);
                s22 += __shfl_xor_sync(0xffffffffu, s22, d);
            }
            if (sub == 0) {
                float* s = sums + j * SUM_STRIDE;
                s[0]  = sw;
                s[1]  = sP0; s[2]  = sP1; s[3]  = sP2;
                s[4]  = sQ0; s[5]  = sQ1; s[6]  = sQ2;
                s[7]  = wP0; s[8]  = wP1; s[9]  = wP2;
                s[10] = wQ0; s[11] = wQ1; s[12] = wQ2;
                s[13] = s00; s[14] = s01; s[15] = s02;
                s[16] = s10; s[17] = s11; s[18] = s12;
                s[19] = s20; s[20] = s21; s[21] = s22;
            }
        }
        __syncthreads();

        // ---- Solve: warp 0, one j per lane (overlaps next batch's DMA) ----
        if (tid < J_N) {
            const float* s = sums + tid * SUM_STRIDE;
            float Tsw = s[0];
            float TsP0 = s[1],  TsP1 = s[2],  TsP2 = s[3];
            float TsQ0 = s[4],  TsQ1 = s[5],  TsQ2 = s[6];
            float TwP0 = s[7],  TwP1 = s[8],  TwP2 = s[9];
            float TwQ0 = s[10], TwQ1 = s[11], TwQ2 = s[12];
            float t00 = s[13], t01 = s[14], t02 = s[15];
            float t10 = s[16], t11 = s[17], t12 = s[18];
            float t20 = s[19], t21 = s[20], t22 = s[21];

            float inv = 1.0f / Tsw;
            float Pb0 = TwP0 * inv, Pb1 = TwP1 * inv, Pb2 = TwP2 * inv;
            float Qb0 = TwQ0 * inv, Qb1 = TwQ1 * inv, Qb2 = TwQ2 * inv;

            float g0 = TsP0 - (float)M_N * Pb0;
            float g1 = TsP1 - (float)M_N * Pb1;
            float g2 = TsP2 - (float)M_N * Pb2;

            float Sxx = t00 - Pb0 * TsQ0 - g0 * Qb0;
            float Sxy = t01 - Pb0 * TsQ1 - g0 * Qb1;
            float Sxz = t02 - Pb0 * TsQ2 - g0 * Qb2;
            float Syx = t10 - Pb1 * TsQ0 - g1 * Qb0;
            float Syy = t11 - Pb1 * TsQ1 - g1 * Qb1;
            float Syz = t12 - Pb1 * TsQ2 - g1 * Qb2;
            float Szx = t20 - Pb2 * TsQ0 - g2 * Qb0;
            float Szy = t21 - Pb2 * TsQ1 - g2 * Qb1;
            float Szz = t22 - Pb2 * TsQ2 - g2 * Qb2;

            float n00 = Sxx + Syy + Szz;
            float n01 = Syz - Szy;
            float n02 = Szx - Sxz;
            float n03 = Sxy - Syx;
            float n11 = Sxx - Syy - Szz;
            float n12 = Sxy + Syx;
            float n13 = Szx + Sxz;
            float n22 = -Sxx + Syy - Szz;
            float n23 = Syz + Szy;
            float n33 = -Sxx - Syy + Szz;

            float f2 = n00 * n00 + n11 * n11 + n22 * n22 + n33 * n33 +
                       2.0f * (n01 * n01 + n02 * n02 + n03 * n03 +
                               n12 * n12 + n13 * n13 + n23 * n23);
            float sh = sqrtf(f2) + 1e-30f;

            float b00 = n00 + sh, b01 = n01, b02 = n02, b03 = n03;
            float b11 = n11 + sh, b12 = n12, b13 = n13;
            float b22 = n22 + sh, b23 = n23;
            float b33 = n33 + sh;

#pragma unroll 1
            for (int it = 0; it < 16; ++it) {
                float c00 = b00 * b00 + b01 * b01 + b02 * b02 + b03 * b03;
                float c01 = b00 * b01 + b01 * b11 + b02 * b12 + b03 * b13;
                float c02 = b00 * b02 + b01 * b12 + b02 * b22 + b03 * b23;
                float c03 = b00 * b03 + b01 * b13 + b02 * b23 + b03 * b33;
                float c11 = b01 * b01 + b11 * b11 + b12 * b12 + b13 * b13;
                float c12 = b01 * b02 + b11 * b12 + b12 * b22 + b13 * b23;
                float c13 = b01 * b03 + b11 * b13 + b12 * b23 + b13 * b33;
                float c22 = b02 * b02 + b12 * b12 + b22 * b22 + b23 * b23;
                float c23 = b02 * b03 + b12 * b13 + b22 * b23 + b23 * b33;
                float c33 = b03 * b03 + b13 * b13 + b23 * b23 + b33 * b33;
                float tr = c00 + c11 + c22 + c33;
                float sc = __frcp_rn(tr);
                b00 = c00 * sc; b01 = c01 * sc; b02 = c02 * sc; b03 = c03 * sc;
                b11 = c11 * sc; b12 = c12 * sc; b13 = c13 * sc;
                b22 = c22 * sc; b23 = c23 * sc;
                b33 = c33 * sc;
            }

            float q0, q1, q2, q3;
            if (b00 >= b11 && b00 >= b22 && b00 >= b33) {
                q0 = b00; q1 = b01; q2 = b02; q3 = b03;
            } else if (b11 >= b22 && b11 >= b33) {
                q0 = b01; q1 = b11; q2 = b12; q3 = b13;
            } else if (b22 >= b33) {
                q0 = b02; q1 = b12; q2 = b22; q3 = b23;
            } else {
                q0 = b03; q1 = b13; q2 = b23; q3 = b33;
            }
            float nq = rsqrtf(q0 * q0 + q1 * q1 + q2 * q2 + q3 * q3);
            q0 *= nq; q1 *= nq; q2 *= nq; q3 *= nq;

            float xx = q1 * q1, yy = q2 * q2, zz = q3 * q3;
            float xy = q1 * q2, xz = q1 * q3, yz = q2 * q3;
            float wx = q0 * q1, wy = q0 * q2, wz = q0 * q3;

            float R00 = 1.0f - 2.0f * (yy + zz);
            float R01 = 2.0f * (xy - wz);
            float R02 = 2.0f * (xz + wy);
            float R10 = 2.0f * (xy + wz);
            float R11 = 1.0f - 2.0f * (xx + zz);
            float R12 = 2.0f * (yz - wx);
            float R20 = 2.0f * (xz - wy);
            float R21 = 2.0f * (yz + wx);
            float R22 = 1.0f - 2.0f * (xx + yy);

            float tx = Qb0 - (R00 * Pb0 + R01 * Pb1 + R02 * Pb2);
            float ty = Qb1 - (R10 * Pb0 + R11 * Pb1 + R12 * Pb2);
            float tz = Qb2 - (R20 * Pb0 + R21 * Pb1 + R22 * Pb2);

            const int grp_out = (b0 + i) * J_N + tid;
            float* oR = out + (size_t)grp_out * 9;
            oR[0] = R00; oR[1] = R01; oR[2] = R02;
            oR[3] = R10; oR[4] = R11; oR[5] = R12;
            oR[6] = R20; oR[7] = R21; oR[8] = R22;

            float* oT = out + (size_t)B_N * J_N * 9 + (size_t)grp_out * 3;
            oT[0] = tx; oT[1] = ty; oT[2] = tz;
        }
        __syncthreads();   // sums buffer free before next batch's butterfly
    }
}

extern "C" void kernel_launch(void* const* d_in, const int* in_sizes, int n_in,
                              void* d_out, int out_size)
{
    const float* points = (const float*)d_in[0];
    const float* weight = (const float*)d_in[1];
    const float* offset = (const float*)d_in[2];
    float* out = (float*)d_out;

    svd_solver_kernel<<<GRID, 128>>>(points, weight, offset, out);
}

// round 10
// speedup vs baseline: 1.6057x; 1.2385x over previous
#include <cuda_runtime.h>
#include <cuda_bf16.h>
#include <cstdint>

// SVD_Solver: batched weighted Kabsch via Horn quaternion method.
// points (B,M,3) f32, weight (B,M,J) f32, offset (B,M,J,3) f32.
// out = [R (B,J,3,3) ; t (B,J,3)], f32.
//
// R10: R7 structure, occupancy-maxed. 96-thread blocks (every warp computes),
// offset staged in 4.6KB QUARTERS, double-buffered (9.2KB) -> ~11.9KB smem.
// Reg-capped at 13 CTAs/SM => 39 all-compute warps/SM (vs R7's 27).

#define B_N 4096
#define M_N 64
#define J_N 24

#define O_QTR (16 * J_N * 3)        // 1152 floats = 4608 B per quarter
#define Q_FLOATS (M_N * 3)          // 192
#define SUM_STRIDE 23               // 22 sums + pad, gcd(23,32)=1

__device__ __forceinline__ void cp_async16(uint32_t smem_addr, const void* gptr) {
    asm volatile("cp.async.cg.shared.global [%0], [%1], 16;\n"
                 :: "r"(smem_addr), "l"(gptr));
}
__device__ __forceinline__ void cp_commit() {
    asm volatile("cp.async.commit_group;\n");
}
template <int N>
__device__ __forceinline__ void cp_wait() {
    asm volatile("cp.async.wait_group %0;\n" :: "n"(N));
}

__global__ void __launch_bounds__(96, 13)
svd_solver_kernel(const float* __restrict__ points,
                  const float* __restrict__ weight,
                  const float* __restrict__ offset,
                  float* __restrict__ out)
{
    __shared__ __align__(16) float smo[2 * O_QTR];   // two quarter slots
    __shared__ __align__(16) float smq[Q_FLOATS];
    __shared__ float sums[J_N * SUM_STRIDE];

    const int tid = threadIdx.x;
    const int b = blockIdx.x;

    const float* go = offset + (size_t)b * (M_N * J_N * 3);
    const float* gw = weight + (size_t)b * (M_N * J_N);
    const float* gq = points + (size_t)b * Q_FLOATS;

    const uint32_t so = (uint32_t)__cvta_generic_to_shared(smo);
    const uint32_t sq = (uint32_t)__cvta_generic_to_shared(smq);

    // Issue quarter qi (16 m-rows) into slot (0/1). 288 float4s / 96 thr.
    auto issue_q = [&](int qi, int slot) {
        const float* src = go + qi * O_QTR;
        const uint32_t dst = so + slot * (O_QTR * 4);
#pragma unroll
        for (int k = 0; k < 3; ++k) {
            int idx = k * 96 + tid;
            cp_async16(dst + idx * 16, src + idx * 4);
        }
    };

    // Prologue: q0 (+points) as group0, q1 as group1.
    issue_q(0, 0);
    if (tid < Q_FLOATS / 4)
        cp_async16(sq + tid * 16, gq + tid * 4);
    cp_commit();
    issue_q(1, 1);
    cp_commit();

    const int j = tid >> 2;          // 0..23
    const int sub = tid & 3;

    float sw = 0.f;
    float sP0 = 0.f, sP1 = 0.f, sP2 = 0.f;
    float sQ0 = 0.f, sQ1 = 0.f, sQ2 = 0.f;
    float wP0 = 0.f, wP1 = 0.f, wP2 = 0.f;
    float wQ0 = 0.f, wQ1 = 0.f, wQ2 = 0.f;
    float s00 = 0.f, s01 = 0.f, s02 = 0.f;
    float s10 = 0.f, s11 = 0.f, s12 = 0.f;
    float s20 = 0.f, s21 = 0.f, s22 = 0.f;

#pragma unroll 1
    for (int q = 0; q < 4; ++q) {
        if (q < 3) cp_wait<1>(); else cp_wait<0>();
        __syncthreads();

        const int mbase = q * 16;
        const float* ob = smo + (q & 1) * O_QTR;

        // Hoisted global weight loads for this quarter (4 in flight).
        float wreg[4];
#pragma unroll
        for (int ml = 0; ml < 4; ++ml)
            wreg[ml] = gw[(mbase + ml * 4 + sub) * J_N + j];

#pragma unroll
        for (int ml = 0; ml < 4; ++ml) {
            const int m_local = ml * 4 + sub;
            const float* po = ob + (m_local * J_N + j) * 3;
            float p0 = po[0], p1 = po[1], p2 = po[2];
            const float* pq = smq + (mbase + m_local) * 3;
            float q0 = pq[0], q1 = pq[1], q2 = pq[2];
            float w = wreg[ml];

            sw += w;
            sP0 += p0; sP1 += p1; sP2 += p2;
            sQ0 += q0; sQ1 += q1; sQ2 += q2;
            wP0 = fmaf(w, p0, wP0); wP1 = fmaf(w, p1, wP1); wP2 = fmaf(w, p2, wP2);
            wQ0 = fmaf(w, q0, wQ0); wQ1 = fmaf(w, q1, wQ1); wQ2 = fmaf(w, q2, wQ2);
            s00 = fmaf(p0, q0, s00); s01 = fmaf(p0, q1, s01); s02 = fmaf(p0, q2, s02);
            s10 = fmaf(p1, q0, s10); s11 = fmaf(p1, q1, s11); s12 = fmaf(p1, q2, s12);
            s20 = fmaf(p2, q0, s20); s21 = fmaf(p2, q1, s21); s22 = fmaf(p2, q2, s22);
        }
        __syncthreads();             // slot (q&1) fully consumed

        if (q + 2 < 4) {
            issue_q(q + 2, q & 1);   // refill freed slot
            cp_commit();
        }
    }

    // Butterfly across the 4 adjacent-lane sub partners.
#pragma unroll
    for (int d = 1; d < 4; d <<= 1) {
        sw  += __shfl_xor_sync(0xffffffffu, sw,  d);
        sP0 += __shfl_xor_sync(0xffffffffu, sP0, d);
        sP1 += __shfl_xor_sync(0xffffffffu, sP1, d);
        sP2 += __shfl_xor_sync(0xffffffffu, sP2, d);
        sQ0 += __shfl_xor_sync(0xffffffffu, sQ0, d);
        sQ1 += __shfl_xor_sync(0xffffffffu, sQ1, d);
        sQ2 += __shfl_xor_sync(0xffffffffu, sQ2, d);
        wP0 += __shfl_xor_sync(0xffffffffu, wP0, d);
        wP1 += __shfl_xor_sync(0xffffffffu, wP1, d);
        wP2 += __shfl_xor_sync(0xffffffffu, wP2, d);
        wQ0 += __shfl_xor_sync(0xffffffffu, wQ0, d);
        wQ1 += __shfl_xor_sync(0xffffffffu, wQ1, d);
        wQ2 += __shfl_xor_sync(0xffffffffu, wQ2, d);
        s00 += __shfl_xor_sync(0xffffffffu, s00, d);
        s01 += __shfl_xor_sync(0xffffffffu, s01, d);
        s02 += __shfl_xor_sync(0xffffffffu, s02, d);
        s10 += __shfl_xor_sync(0xffffffffu, s10, d);
        s11 += __shfl_xor_sync(0xffffffffu, s11, d);
        s12 += __shfl_xor_sync(0xffffffffu, s12, d);
        s20 += __shfl_xor_sync(0xffffffffu, s20, d);
        s21 += __shfl_xor_sync(0xffffffffu, s21, d);
        s22 += __shfl_xor_sync(0xffffffffu, s22, d);
    }
    if (sub == 0) {
        float* s = sums + j * SUM_STRIDE;
        s[0]  = sw;
        s[1]  = sP0; s[2]  = sP1; s[3]  = sP2;
        s[4]  = sQ0; s[5]  = sQ1; s[6]  = sQ2;
        s[7]  = wP0; s[8]  = wP1; s[9]  = wP2;
        s[10] = wQ0; s[11] = wQ1; s[12] = wQ2;
        s[13] = s00; s[14] = s01; s[15] = s02;
        s[16] = s10; s[17] = s11; s[18] = s12;
        s[19] = s20; s[20] = s21; s[21] = s22;
    }
    __syncthreads();

    if (tid >= J_N) return;

    // ---- Solve: warp 0, one j per lane ----
    const float* s = sums + tid * SUM_STRIDE;
    float Tsw = s[0];
    float TsP0 = s[1],  TsP1 = s[2],  TsP2 = s[3];
    float TsQ0 = s[4],  TsQ1 = s[5],  TsQ2 = s[6];
    float TwP0 = s[7],  TwP1 = s[8],  TwP2 = s[9];
    float TwQ0 = s[10], TwQ1 = s[11], TwQ2 = s[12];
    float t00 = s[13], t01 = s[14], t02 = s[15];
    float t10 = s[16], t11 = s[17], t12 = s[18];
    float t20 = s[19], t21 = s[20], t22 = s[21];

    float inv = 1.0f / Tsw;
    float Pb0 = TwP0 * inv, Pb1 = TwP1 * inv, Pb2 = TwP2 * inv;
    float Qb0 = TwQ0 * inv, Qb1 = TwQ1 * inv, Qb2 = TwQ2 * inv;

    float g0 = TsP0 - (float)M_N * Pb0;
    float g1 = TsP1 - (float)M_N * Pb1;
    float g2 = TsP2 - (float)M_N * Pb2;

    float Sxx = t00 - Pb0 * TsQ0 - g0 * Qb0;
    float Sxy = t01 - Pb0 * TsQ1 - g0 * Qb1;
    float Sxz = t02 - Pb0 * TsQ2 - g0 * Qb2;
    float Syx = t10 - Pb1 * TsQ0 - g1 * Qb0;
    float Syy = t11 - Pb1 * TsQ1 - g1 * Qb1;
    float Syz = t12 - Pb1 * TsQ2 - g1 * Qb2;
    float Szx = t20 - Pb2 * TsQ0 - g2 * Qb0;
    float Szy = t21 - Pb2 * TsQ1 - g2 * Qb1;
    float Szz = t22 - Pb2 * TsQ2 - g2 * Qb2;

    float n00 = Sxx + Syy + Szz;
    float n01 = Syz - Szy;
    float n02 = Szx - Sxz;
    float n03 = Sxy - Syx;
    float n11 = Sxx - Syy - Szz;
    float n12 = Sxy + Syx;
    float n13 = Szx + Sxz;
    float n22 = -Sxx + Syy - Szz;
    float n23 = Syz + Szy;
    float n33 = -Sxx - Syy + Szz;

    float f2 = n00 * n00 + n11 * n11 + n22 * n22 + n33 * n33 +
               2.0f * (n01 * n01 + n02 * n02 + n03 * n03 +
                       n12 * n12 + n13 * n13 + n23 * n23);
    float sh = sqrtf(f2) + 1e-30f;

    float b00 = n00 + sh, b01 = n01, b02 = n02, b03 = n03;
    float b11 = n11 + sh, b12 = n12, b13 = n13;
    float b22 = n22 + sh, b23 = n23;
    float b33 = n33 + sh;

#pragma unroll 1
    for (int it = 0; it < 16; ++it) {
        float c00 = b00 * b00 + b01 * b01 + b02 * b02 + b03 * b03;
        float c01 = b00 * b01 + b01 * b11 + b02 * b12 + b03 * b13;
        float c02 = b00 * b02 + b01 * b12 + b02 * b22 + b03 * b23;
        float c03 = b00 * b03 + b01 * b13 + b02 * b23 + b03 * b33;
        float c11 = b01 * b01 + b11 * b11 + b12 * b12 + b13 * b13;
        float c12 = b01 * b02 + b11 * b12 + b12 * b22 + b13 * b23;
        float c13 = b01 * b03 + b11 * b13 + b12 * b23 + b13 * b33;
        float c22 = b02 * b02 + b12 * b12 + b22 * b22 + b23 * b23;
        float c23 = b02 * b03 + b12 * b13 + b22 * b23 + b23 * b33;
        float c33 = b03 * b03 + b13 * b13 + b23 * b23 + b33 * b33;
        float tr = c00 + c11 + c22 + c33;
        float sc = __frcp_rn(tr);
        b00 = c00 * sc; b01 = c01 * sc; b02 = c02 * sc; b03 = c03 * sc;
        b11 = c11 * sc; b12 = c12 * sc; b13 = c13 * sc;
        b22 = c22 * sc; b23 = c23 * sc;
        b33 = c33 * sc;
    }

    float q0, q1, q2, q3;
    if (b00 >= b11 && b00 >= b22 && b00 >= b33) {
        q0 = b00; q1 = b01; q2 = b02; q3 = b03;
    } else if (b11 >= b22 && b11 >= b33) {
        q0 = b01; q1 = b11; q2 = b12; q3 = b13;
    } else if (b22 >= b33) {
        q0 = b02; q1 = b12; q2 = b22; q3 = b23;
    } else {
        q0 = b03; q1 = b13; q2 = b23; q3 = b33;
    }
    float nq = rsqrtf(q0 * q0 + q1 * q1 + q2 * q2 + q3 * q3);
    q0 *= nq; q1 *= nq; q2 *= nq; q3 *= nq;

    float xx = q1 * q1, yy = q2 * q2, zz = q3 * q3;
    float xy = q1 * q2, xz = q1 * q3, yz = q2 * q3;
    float wx = q0 * q1, wy = q0 * q2, wz = q0 * q3;

    float R00 = 1.0f - 2.0f * (yy + zz);
    float R01 = 2.0f * (xy - wz);
    float R02 = 2.0f * (xz + wy);
    float R10 = 2.0f * (xy + wz);
    float R11 = 1.0f - 2.0f * (xx + zz);
    float R12 = 2.0f * (yz - wx);
    float R20 = 2.0f * (xz - wy);
    float R21 = 2.0f * (yz + wx);
    float R22 = 1.0f - 2.0f * (xx + yy);

    float tx = Qb0 - (R00 * Pb0 + R01 * Pb1 + R02 * Pb2);
    float ty = Qb1 - (R10 * Pb0 + R11 * Pb1 + R12 * Pb2);
    float tz = Qb2 - (R20 * Pb0 + R21 * Pb1 + R22 * Pb2);

    const int grp_out = b * J_N + tid;
    float* oR = out + (size_t)grp_out * 9;
    oR[0] = R00; oR[1] = R01; oR[2] = R02;
    oR[3] = R10; oR[4] = R11; oR[5] = R12;
    oR[6] = R20; oR[7] = R21; oR[8] = R22;

    float* oT = out + (size_t)B_N * J_N * 9 + (size_t)grp_out * 3;
    oT[0] = tx; oT[1] = ty; oT[2] = tz;
}

extern "C" void kernel_launch(void* const* d_in, const int* in_sizes, int n_in,
                              void* d_out, int out_size)
{
    const float* points = (const float*)d_in[0];
    const float* weight = (const float*)d_in[1];
    const float* offset = (const float*)d_in[2];
    float* out = (float*)d_out;

    svd_solver_kernel<<<B_N, 96>>>(points, weight, offset, out);
}

// round 11
// speedup vs baseline: 1.7347x; 1.0804x over previous
#include <cuda_runtime.h>
#include <cuda_bf16.h>
#include <cstdint>

// SVD_Solver: batched weighted Kabsch.
// points (B,M,3) f32, weight (B,M,J) f32, offset (B,M,J,3) f32.
// out = [R (B,J,3,3) ; t (B,J,3)], f32.
//
// R11: R10 reduction (96-thr blocks, quarter-staged cp.async, 13 CTAs/SM)
// + Theobald QCP solve: Newton on the quartic char. poly of Horn's N for
// lambda_max, eigenvector from adjugate of (N - lambda I). ~420 instr vs
// ~1100 for the old 16x matrix-squaring -> shorter CTA tail, faster churn.

#define B_N 4096
#define M_N 64
#define J_N 24

#define O_QTR (16 * J_N * 3)        // 1152 floats = 4608 B per quarter
#define Q_FLOATS (M_N * 3)          // 192
#define SUM_STRIDE 23               // 22 sums + pad, gcd(23,32)=1

__device__ __forceinline__ void cp_async16(uint32_t smem_addr, const void* gptr) {
    asm volatile("cp.async.cg.shared.global [%0], [%1], 16;\n"
                 :: "r"(smem_addr), "l"(gptr));
}
__device__ __forceinline__ void cp_commit() {
    asm volatile("cp.async.commit_group;\n");
}
template <int N>
__device__ __forceinline__ void cp_wait() {
    asm volatile("cp.async.wait_group %0;\n" :: "n"(N));
}

__global__ void __launch_bounds__(96, 13)
svd_solver_kernel(const float* __restrict__ points,
                  const float* __restrict__ weight,
                  const float* __restrict__ offset,
                  float* __restrict__ out)
{
    __shared__ __align__(16) float smo[2 * O_QTR];   // two quarter slots
    __shared__ __align__(16) float smq[Q_FLOATS];
    __shared__ float sums[J_N * SUM_STRIDE];

    const int tid = threadIdx.x;
    const int b = blockIdx.x;

    const float* go = offset + (size_t)b * (M_N * J_N * 3);
    const float* gw = weight + (size_t)b * (M_N * J_N);
    const float* gq = points + (size_t)b * Q_FLOATS;

    const uint32_t so = (uint32_t)__cvta_generic_to_shared(smo);
    const uint32_t sq = (uint32_t)__cvta_generic_to_shared(smq);

    auto issue_q = [&](int qi, int slot) {
        const float* src = go + qi * O_QTR;
        const uint32_t dst = so + slot * (O_QTR * 4);
#pragma unroll
        for (int k = 0; k < 3; ++k) {
            int idx = k * 96 + tid;
            cp_async16(dst + idx * 16, src + idx * 4);
        }
    };

    issue_q(0, 0);
    if (tid < Q_FLOATS / 4)
        cp_async16(sq + tid * 16, gq + tid * 4);
    cp_commit();
    issue_q(1, 1);
    cp_commit();

    const int j = tid >> 2;
    const int sub = tid & 3;

    float sw = 0.f;
    float sP0 = 0.f, sP1 = 0.f, sP2 = 0.f;
    float sQ0 = 0.f, sQ1 = 0.f, sQ2 = 0.f;
    float wP0 = 0.f, wP1 = 0.f, wP2 = 0.f;
    float wQ0 = 0.f, wQ1 = 0.f, wQ2 = 0.f;
    float s00 = 0.f, s01 = 0.f, s02 = 0.f;
    float s10 = 0.f, s11 = 0.f, s12 = 0.f;
    float s20 = 0.f, s21 = 0.f, s22 = 0.f;

#pragma unroll 1
    for (int q = 0; q < 4; ++q) {
        if (q < 3) cp_wait<1>(); else cp_wait<0>();
        __syncthreads();

        const int mbase = q * 16;
        const float* ob = smo + (q & 1) * O_QTR;

        float wreg[4];
#pragma unroll
        for (int ml = 0; ml < 4; ++ml)
            wreg[ml] = gw[(mbase + ml * 4 + sub) * J_N + j];

#pragma unroll
        for (int ml = 0; ml < 4; ++ml) {
            const int m_local = ml * 4 + sub;
            const float* po = ob + (m_local * J_N + j) * 3;
            float p0 = po[0], p1 = po[1], p2 = po[2];
            const float* pq = smq + (mbase + m_local) * 3;
            float q0 = pq[0], q1 = pq[1], q2 = pq[2];
            float w = wreg[ml];

            sw += w;
            sP0 += p0; sP1 += p1; sP2 += p2;
            sQ0 += q0; sQ1 += q1; sQ2 += q2;
            wP0 = fmaf(w, p0, wP0); wP1 = fmaf(w, p1, wP1); wP2 = fmaf(w, p2, wP2);
            wQ0 = fmaf(w, q0, wQ0); wQ1 = fmaf(w, q1, wQ1); wQ2 = fmaf(w, q2, wQ2);
            s00 = fmaf(p0, q0, s00); s01 = fmaf(p0, q1, s01); s02 = fmaf(p0, q2, s02);
            s10 = fmaf(p1, q0, s10); s11 = fmaf(p1, q1, s11); s12 = fmaf(p1, q2, s12);
            s20 = fmaf(p2, q0, s20); s21 = fmaf(p2, q1, s21); s22 = fmaf(p2, q2, s22);
        }
        __syncthreads();

        if (q + 2 < 4) {
            issue_q(q + 2, q & 1);
            cp_commit();
        }
    }

#pragma unroll
    for (int d = 1; d < 4; d <<= 1) {
        sw  += __shfl_xor_sync(0xffffffffu, sw,  d);
        sP0 += __shfl_xor_sync(0xffffffffu, sP0, d);
        sP1 += __shfl_xor_sync(0xffffffffu, sP1, d);
        sP2 += __shfl_xor_sync(0xffffffffu, sP2, d);
        sQ0 += __shfl_xor_sync(0xffffffffu, sQ0, d);
        sQ1 += __shfl_xor_sync(0xffffffffu, sQ1, d);
        sQ2 += __shfl_xor_sync(0xffffffffu, sQ2, d);
        wP0 += __shfl_xor_sync(0xffffffffu, wP0, d);
        wP1 += __shfl_xor_sync(0xffffffffu, wP1, d);
        wP2 += __shfl_xor_sync(0xffffffffu, wP2, d);
        wQ0 += __shfl_xor_sync(0xffffffffu, wQ0, d);
        wQ1 += __shfl_xor_sync(0xffffffffu, wQ1, d);
        wQ2 += __shfl_xor_sync(0xffffffffu, wQ2, d);
        s00 += __shfl_xor_sync(0xffffffffu, s00, d);
        s01 += __shfl_xor_sync(0xffffffffu, s01, d);
        s02 += __shfl_xor_sync(0xffffffffu, s02, d);
        s10 += __shfl_xor_sync(0xffffffffu, s10, d);
        s11 += __shfl_xor_sync(0xffffffffu, s11, d);
        s12 += __shfl_xor_sync(0xffffffffu, s12, d);
        s20 += __shfl_xor_sync(0xffffffffu, s20, d);
        s21 += __shfl_xor_sync(0xffffffffu, s21, d);
        s22 += __shfl_xor_sync(0xffffffffu, s22, d);
    }
    if (sub == 0) {
        float* s = sums + j * SUM_STRIDE;
        s[0]  = sw;
        s[1]  = sP0; s[2]  = sP1; s[3]  = sP2;
        s[4]  = sQ0; s[5]  = sQ1; s[6]  = sQ2;
        s[7]  = wP0; s[8]  = wP1; s[9]  = wP2;
        s[10] = wQ0; s[11] = wQ1; s[12] = wQ2;
        s[13] = s00; s[14] = s01; s[15] = s02;
        s[16] = s10; s[17] = s11; s[18] = s12;
        s[19] = s20; s[20] = s21; s[21] = s22;
    }
    __syncthreads();

    if (tid >= J_N) return;

    // ---- Solve (QCP): warp 0, one j per lane ----
    const float* s = sums + tid * SUM_STRIDE;
    float Tsw = s[0];
    float TsP0 = s[1],  TsP1 = s[2],  TsP2 = s[3];
    float TsQ0 = s[4],  TsQ1 = s[5],  TsQ2 = s[6];
    float TwP0 = s[7],  TwP1 = s[8],  TwP2 = s[9];
    float TwQ0 = s[10], TwQ1 = s[11], TwQ2 = s[12];
    float t00 = s[13], t01 = s[14], t02 = s[15];
    float t10 = s[16], t11 = s[17], t12 = s[18];
    float t20 = s[19], t21 = s[20], t22 = s[21];

    float inv = 1.0f / Tsw;
    float Pb0 = TwP0 * inv, Pb1 = TwP1 * inv, Pb2 = TwP2 * inv;
    float Qb0 = TwQ0 * inv, Qb1 = TwQ1 * inv, Qb2 = TwQ2 * inv;

    float g0 = TsP0 - (float)M_N * Pb0;
    float g1 = TsP1 - (float)M_N * Pb1;
    float g2 = TsP2 - (float)M_N * Pb2;

    float Sxx = t00 - Pb0 * TsQ0 - g0 * Qb0;
    float Sxy = t01 - Pb0 * TsQ1 - g0 * Qb1;
    float Sxz = t02 - Pb0 * TsQ2 - g0 * Qb2;
    float Syx = t10 - Pb1 * TsQ0 - g1 * Qb0;
    float Syy = t11 - Pb1 * TsQ1 - g1 * Qb1;
    float Syz = t12 - Pb1 * TsQ2 - g1 * Qb2;
    float Szx = t20 - Pb2 * TsQ0 - g2 * Qb0;
    float Szy = t21 - Pb2 * TsQ1 - g2 * Qb1;
    float Szz = t22 - Pb2 * TsQ2 - g2 * Qb2;

    // Quartic coefficients: P(l) = l^4 + C2 l^2 + C1 l + C0
    float P2 = Sxx*Sxx + Sxy*Sxy + Sxz*Sxz + Syx*Syx + Syy*Syy + Syz*Syz
             + Szx*Szx + Szy*Szy + Szz*Szz;                  // tr(S^T S)
    float C2 = -2.0f * P2;
    float detS = Sxx * (Syy * Szz - Syz * Szy)
               - Sxy * (Syx * Szz - Syz * Szx)
               + Sxz * (Syx * Szy - Syy * Szx);
    float C1 = -8.0f * detS;
    // M = S^T S (columns of S dotted)
    float M00 = Sxx*Sxx + Syx*Syx + Szx*Szx;
    float M11 = Sxy*Sxy + Syy*Syy + Szy*Szy;
    float M22 = Sxz*Sxz + Syz*Syz + Szz*Szz;
    float M01 = Sxx*Sxy + Syx*Syy + Szx*Szy;
    float M02 = Sxx*Sxz + Syx*Syz + Szx*Szz;
    float M12 = Sxy*Sxz + Syy*Syz + Szy*Szz;
    float trM2 = M00*M00 + M11*M11 + M22*M22
               + 2.0f * (M01*M01 + M02*M02 + M12*M12);       // tr((S^T S)^2)
    float C0 = 2.0f * trM2 - P2 * P2;

    // Newton from upper bound l0 = sqrt(3 * tr(S^T S)) >= smax sum
    float lam = sqrtf(3.0f * P2);
#pragma unroll
    for (int it = 0; it < 10; ++it) {
        float l2 = lam * lam;
        float f  = (l2 + C2) * l2 + C1 * lam + C0;
        float fp = (4.0f * l2 + 2.0f * C2) * lam + C1;
        lam -= f / (fp + 1e-20f);
    }

    // Horn's N, K = N - lam I
    float n00 = Sxx + Syy + Szz;
    float n01 = Syz - Szy;
    float n02 = Szx - Sxz;
    float n03 = Sxy - Syx;
    float n11 = Sxx - Syy - Szz;
    float n12 = Sxy + Syx;
    float n13 = Szx + Sxz;
    float n22 = -Sxx + Syy - Szz;
    float n23 = Syz + Szy;
    float n33 = -Sxx - Syy + Szz;

    float k00 = n00 - lam, k01 = n01, k02 = n02, k03 = n03;
    float k11 = n11 - lam, k12 = n12, k13 = n13;
    float k22 = n22 - lam, k23 = n23;
    float k33 = n33 - lam;

    // Symmetric adjugate of K (= c * q q^T); all 10 unique entries.
    float a00 = k11*(k22*k33 - k23*k23) - k12*(k12*k33 - k13*k23) + k13*(k12*k23 - k13*k22);
    float a11 = k00*(k22*k33 - k23*k23) - k02*(k02*k33 - k03*k23) + k03*(k02*k23 - k03*k22);
    float a22 = k00*(k11*k33 - k13*k13) - k01*(k01*k33 - k03*k13) + k03*(k01*k13 - k03*k11);
    float a33 = k00*(k11*k22 - k12*k12) - k01*(k01*k22 - k02*k12) + k02*(k01*k12 - k02*k11);
    float a01 = -(k01*(k22*k33 - k23*k23) - k12*(k02*k33 - k03*k23) + k13*(k02*k23 - k03*k22));
    float a02 =   k01*(k12*k33 - k23*k13) - k11*(k02*k33 - k23*k03) + k13*(k02*k13 - k12*k03);
    float a03 = -(k01*(k12*k23 - k22*k13) - k11*(k02*k23 - k22*k03) + k12*(k02*k13 - k12*k03));
    float a12 = -(k00*(k12*k33 - k23*k13) - k01*(k02*k33 - k23*k03) + k03*(k02*k13 - k12*k03));
    float a13 =   k00*(k12*k23 - k22*k13) - k01*(k02*k23 - k22*k03) + k02*(k02*k13 - k12*k03);
    float a23 = -(k00*(k11*k23 - k12*k13) - k01*(k01*k23 - k12*k03) + k02*(k01*k13 - k11*k03));

    // Pick column with largest |diagonal| (diag = c * q_i^2).
    float q0, q1, q2, q3;
    float m0 = fabsf(a00), m1 = fabsf(a11), m2 = fabsf(a22), m3 = fabsf(a33);
    if (m0 >= m1 && m0 >= m2 && m0 >= m3) {
        q0 = a00; q1 = a01; q2 = a02; q3 = a03;
    } else if (m1 >= m2 && m1 >= m3) {
        q0 = a01; q1 = a11; q2 = a12; q3 = a13;
    } else if (m2 >= m3) {
        q0 = a02; q1 = a12; q2 = a22; q3 = a23;
    } else {
        q0 = a03; q1 = a13; q2 = a23; q3 = a33;
    }
    float nq = rsqrtf(q0*q0 + q1*q1 + q2*q2 + q3*q3 + 1e-30f);
    q0 *= nq; q1 *= nq; q2 *= nq; q3 *= nq;

    float xx = q1 * q1, yy = q2 * q2, zz = q3 * q3;
    float xy = q1 * q2, xz = q1 * q3, yz = q2 * q3;
    float wx = q0 * q1, wy = q0 * q2, wz = q0 * q3;

    float R00 = 1.0f - 2.0f * (yy + zz);
    float R01 = 2.0f * (xy - wz);
    float R02 = 2.0f * (xz + wy);
    float R10 = 2.0f * (xy + wz);
    float R11 = 1.0f - 2.0f * (xx + zz);
    float R12 = 2.0f * (yz - wx);
    float R20 = 2.0f * (xz - wy);
    float R21 = 2.0f * (yz + wx);
    float R22 = 1.0f - 2.0f * (xx + yy);

    float tx = Qb0 - (R00 * Pb0 + R01 * Pb1 + R02 * Pb2);
    float ty = Qb1 - (R10 * Pb0 + R11 * Pb1 + R12 * Pb2);
    float tz = Qb2 - (R20 * Pb0 + R21 * Pb1 + R22 * Pb2);

    const int grp_out = b * J_N + tid;
    float* oR = out + (size_t)grp_out * 9;
    oR[0] = R00; oR[1] = R01; oR[2] = R02;
    oR[3] = R10; oR[4] = R11; oR[5] = R12;
    oR[6] = R20; oR[7] = R21; oR[8] = R22;

    float* oT = out + (size_t)B_N * J_N * 9 + (size_t)grp_out * 3;
    oT[0] = tx; oT[1] = ty; oT[2] = tz;
}

extern "C" void kernel_launch(void* const* d_in, const int* in_sizes, int n_in,
                              void* d_out, int out_size)
{
    const float* points = (const float*)d_in[0];
    const float* weight = (const float*)d_in[1];
    const float* offset = (const float*)d_in[2];
    float* out = (float*)d_out;

    svd_solver_kernel<<<B_N, 96>>>(points, weight, offset, out);
}

// round 12
// speedup vs baseline: 1.7369x; 1.0013x over previous
#include <cuda_runtime.h>
#include <cuda_bf16.h>
#include <cstdint>

// SVD_Solver: batched weighted Kabsch.
// points (B,M,3) f32, weight (B,M,J) f32, offset (B,M,J,3) f32.
// out = [R (B,J,3,3) ; t (B,J,3)], f32.
//
// R12: R11 + (a) compensated QCP quartic coefficients (error-free P2^2,
// fma-compensated det minors, Horner-fma Newton) to kill the fp32
// cancellation that drove rel_err to 6e-4; (b) launch_bounds (96,14) --
// regs=48 exactly fits 14 CTAs/SM (64512 <= 65536 regs).

#define B_N 4096
#define M_N 64
#define J_N 24

#define O_QTR (16 * J_N * 3)        // 1152 floats = 4608 B per quarter
#define Q_FLOATS (M_N * 3)          // 192
#define SUM_STRIDE 23               // 22 sums + pad, gcd(23,32)=1

__device__ __forceinline__ void cp_async16(uint32_t smem_addr, const void* gptr) {
    asm volatile("cp.async.cg.shared.global [%0], [%1], 16;\n"
                 :: "r"(smem_addr), "l"(gptr));
}
__device__ __forceinline__ void cp_commit() {
    asm volatile("cp.async.commit_group;\n");
}
template <int N>
__device__ __forceinline__ void cp_wait() {
    asm volatile("cp.async.wait_group %0;\n" :: "n"(N));
}

// Compensated difference of products: a*b - c*d with fma error recovery.
__device__ __forceinline__ float diff_prod(float a, float b, float c, float d) {
    float cd = c * d;
    float err = fmaf(-c, d, cd);          // exact: c*d = cd - err
    float dif = fmaf(a, b, -cd);
    return dif + err;
}

__global__ void __launch_bounds__(96, 14)
svd_solver_kernel(const float* __restrict__ points,
                  const float* __restrict__ weight,
                  const float* __restrict__ offset,
                  float* __restrict__ out)
{
    __shared__ __align__(16) float smo[2 * O_QTR];   // two quarter slots
    __shared__ __align__(16) float smq[Q_FLOATS];
    __shared__ float sums[J_N * SUM_STRIDE];

    const int tid = threadIdx.x;
    const int b = blockIdx.x;

    const float* go = offset + (size_t)b * (M_N * J_N * 3);
    const float* gw = weight + (size_t)b * (M_N * J_N);
    const float* gq = points + (size_t)b * Q_FLOATS;

    const uint32_t so = (uint32_t)__cvta_generic_to_shared(smo);
    const uint32_t sq = (uint32_t)__cvta_generic_to_shared(smq);

    auto issue_q = [&](int qi, int slot) {
        const float* src = go + qi * O_QTR;
        const uint32_t dst = so + slot * (O_QTR * 4);
#pragma unroll
        for (int k = 0; k < 3; ++k) {
            int idx = k * 96 + tid;
            cp_async16(dst + idx * 16, src + idx * 4);
        }
    };

    issue_q(0, 0);
    if (tid < Q_FLOATS / 4)
        cp_async16(sq + tid * 16, gq + tid * 4);
    cp_commit();
    issue_q(1, 1);
    cp_commit();

    const int j = tid >> 2;
    const int sub = tid & 3;

    float sw = 0.f;
    float sP0 = 0.f, sP1 = 0.f, sP2 = 0.f;
    float sQ0 = 0.f, sQ1 = 0.f, sQ2 = 0.f;
    float wP0 = 0.f, wP1 = 0.f, wP2 = 0.f;
    float wQ0 = 0.f, wQ1 = 0.f, wQ2 = 0.f;
    float s00 = 0.f, s01 = 0.f, s02 = 0.f;
    float s10 = 0.f, s11 = 0.f, s12 = 0.f;
    float s20 = 0.f, s21 = 0.f, s22 = 0.f;

#pragma unroll 1
    for (int q = 0; q < 4; ++q) {
        if (q < 3) cp_wait<1>(); else cp_wait<0>();
        __syncthreads();

        const int mbase = q * 16;
        const float* ob = smo + (q & 1) * O_QTR;

        float wreg[4];
#pragma unroll
        for (int ml = 0; ml < 4; ++ml)
            wreg[ml] = gw[(mbase + ml * 4 + sub) * J_N + j];

#pragma unroll
        for (int ml = 0; ml < 4; ++ml) {
            const int m_local = ml * 4 + sub;
            const float* po = ob + (m_local * J_N + j) * 3;
            float p0 = po[0], p1 = po[1], p2 = po[2];
            const float* pq = smq + (mbase + m_local) * 3;
            float q0 = pq[0], q1 = pq[1], q2 = pq[2];
            float w = wreg[ml];

            sw += w;
            sP0 += p0; sP1 += p1; sP2 += p2;
            sQ0 += q0; sQ1 += q1; sQ2 += q2;
            wP0 = fmaf(w, p0, wP0); wP1 = fmaf(w, p1, wP1); wP2 = fmaf(w, p2, wP2);
            wQ0 = fmaf(w, q0, wQ0); wQ1 = fmaf(w, q1, wQ1); wQ2 = fmaf(w, q2, wQ2);
            s00 = fmaf(p0, q0, s00); s01 = fmaf(p0, q1, s01); s02 = fmaf(p0, q2, s02);
            s10 = fmaf(p1, q0, s10); s11 = fmaf(p1, q1, s11); s12 = fmaf(p1, q2, s12);
            s20 = fmaf(p2, q0, s20); s21 = fmaf(p2, q1, s21); s22 = fmaf(p2, q2, s22);
        }
        __syncthreads();

        if (q + 2 < 4) {
            issue_q(q + 2, q & 1);
            cp_commit();
        }
    }

#pragma unroll
    for (int d = 1; d < 4; d <<= 1) {
        sw  += __shfl_xor_sync(0xffffffffu, sw,  d);
        sP0 += __shfl_xor_sync(0xffffffffu, sP0, d);
        sP1 += __shfl_xor_sync(0xffffffffu, sP1, d);
        sP2 += __shfl_xor_sync(0xffffffffu, sP2, d);
        sQ0 += __shfl_xor_sync(0xffffffffu, sQ0, d);
        sQ1 += __shfl_xor_sync(0xffffffffu, sQ1, d);
        sQ2 += __shfl_xor_sync(0xffffffffu, sQ2, d);
        wP0 += __shfl_xor_sync(0xffffffffu, wP0, d);
        wP1 += __shfl_xor_sync(0xffffffffu, wP1, d);
        wP2 += __shfl_xor_sync(0xffffffffu, wP2, d);
        wQ0 += __shfl_xor_sync(0xffffffffu, wQ0, d);
        wQ1 += __shfl_xor_sync(0xffffffffu, wQ1, d);
        wQ2 += __shfl_xor_sync(0xffffffffu, wQ2, d);
        s00 += __shfl_xor_sync(0xffffffffu, s00, d);
        s01 += __shfl_xor_sync(0xffffffffu, s01, d);
        s02 += __shfl_xor_sync(0xffffffffu, s02, d);
        s10 += __shfl_xor_sync(0xffffffffu, s10, d);
        s11 += __shfl_xor_sync(0xffffffffu, s11, d);
        s12 += __shfl_xor_sync(0xffffffffu, s12, d);
        s20 += __shfl_xor_sync(0xffffffffu, s20, d);
        s21 += __shfl_xor_sync(0xffffffffu, s21, d);
        s22 += __shfl_xor_sync(0xffffffffu, s22, d);
    }
    if (sub == 0) {
        float* s = sums + j * SUM_STRIDE;
        s[0]  = sw;
        s[1]  = sP0; s[2]  = sP1; s[3]  = sP2;
        s[4]  = sQ0; s[5]  = sQ1; s[6]  = sQ2;
        s[7]  = wP0; s[8]  = wP1; s[9]  = wP2;
        s[10] = wQ0; s[11] = wQ1; s[12] = wQ2;
        s[13] = s00; s[14] = s01; s[15] = s02;
        s[16] = s10; s[17] = s11; s[18] = s12;
        s[19] = s20; s[20] = s21; s[21] = s22;
    }
    __syncthreads();

    if (tid >= J_N) return;

    // ---- Solve (compensated QCP): warp 0, one j per lane ----
    const float* s = sums + tid * SUM_STRIDE;
    float Tsw = s[0];
    float TsP0 = s[1],  TsP1 = s[2],  TsP2 = s[3];
    float TsQ0 = s[4],  TsQ1 = s[5],  TsQ2 = s[6];
    float TwP0 = s[7],  TwP1 = s[8],  TwP2 = s[9];
    float TwQ0 = s[10], TwQ1 = s[11], TwQ2 = s[12];
    float t00 = s[13], t01 = s[14], t02 = s[15];
    float t10 = s[16], t11 = s[17], t12 = s[18];
    float t20 = s[19], t21 = s[20], t22 = s[21];

    float inv = 1.0f / Tsw;
    float Pb0 = TwP0 * inv, Pb1 = TwP1 * inv, Pb2 = TwP2 * inv;
    float Qb0 = TwQ0 * inv, Qb1 = TwQ1 * inv, Qb2 = TwQ2 * inv;

    float g0 = TsP0 - (float)M_N * Pb0;
    float g1 = TsP1 - (float)M_N * Pb1;
    float g2 = TsP2 - (float)M_N * Pb2;

    float Sxx = t00 - Pb0 * TsQ0 - g0 * Qb0;
    float Sxy = t01 - Pb0 * TsQ1 - g0 * Qb1;
    float Sxz = t02 - Pb0 * TsQ2 - g0 * Qb2;
    float Syx = t10 - Pb1 * TsQ0 - g1 * Qb0;
    float Syy = t11 - Pb1 * TsQ1 - g1 * Qb1;
    float Syz = t12 - Pb1 * TsQ2 - g1 * Qb2;
    float Szx = t20 - Pb2 * TsQ0 - g2 * Qb0;
    float Szy = t21 - Pb2 * TsQ1 - g2 * Qb1;
    float Szz = t22 - Pb2 * TsQ2 - g2 * Qb2;

    // Quartic P(l) = l^4 + C2 l^2 + C1 l + C0, compensated coefficients.
    float P2 = Sxx*Sxx + Sxy*Sxy + Sxz*Sxz + Syx*Syx + Syy*Syy + Syz*Syz
             + Szx*Szx + Szy*Szy + Szz*Szz;                  // tr(S^T S), positive sum
    float C2 = -2.0f * P2;

    // detS with compensated 2x2 minors.
    float m0 = diff_prod(Syy, Szz, Syz, Szy);
    float m1 = diff_prod(Syx, Szz, Syz, Szx);
    float m2 = diff_prod(Syx, Szy, Syy, Szx);
    float detS = Sxx * m0 - Sxy * m1 + Sxz * m2;
    float C1 = -8.0f * detS;

    // M = S^T S
    float M00 = Sxx*Sxx + Syx*Syx + Szx*Szx;
    float M11 = Sxy*Sxy + Syy*Syy + Szy*Szy;
    float M22 = Sxz*Sxz + Syz*Syz + Szz*Szz;
    float M01 = Sxx*Sxy + Syx*Syy + Szx*Szy;
    float M02 = Sxx*Sxz + Syx*Syz + Szx*Szz;
    float M12 = Sxy*Sxz + Syy*Syz + Szy*Szz;
    float trM2 = M00*M00 + M11*M11 + M22*M22
               + 2.0f * (M01*M01 + M02*M02 + M12*M12);       // tr((S^T S)^2)

    // C0 = 2*trM2 - P2^2 with error-free P2^2 split (kills cancellation).
    float p  = P2 * P2;
    float pe = fmaf(P2, P2, -p);                  // exact: P2^2 = p + pe
    float C0 = (2.0f * trM2 - p) - pe;

    // Newton from upper bound l0 = sqrt(3 * tr(S^T S)) >= lambda_max.
    float lam = sqrtf(3.0f * P2);
#pragma unroll
    for (int it = 0; it < 10; ++it) {
        float f  = fmaf(fmaf(fmaf(lam, lam, C2), lam, C1), lam, C0);
        float fp = fmaf(fmaf(4.0f * lam, lam, 2.0f * C2), lam, C1);
        lam -= f / (fp + 1e-20f);
    }

    // Horn's N, K = N - lam I
    float n00 = Sxx + Syy + Szz;
    float n01 = Syz - Szy;
    float n02 = Szx - Sxz;
    float n03 = Sxy - Syx;
    float n11 = Sxx - Syy - Szz;
    float n12 = Sxy + Syx;
    float n13 = Szx + Sxz;
    float n22 = -Sxx + Syy - Szz;
    float n23 = Syz + Szy;
    float n33 = -Sxx - Syy + Szz;

    float k00 = n00 - lam, k01 = n01, k02 = n02, k03 = n03;
    float k11 = n11 - lam, k12 = n12, k13 = n13;
    float k22 = n22 - lam, k23 = n23;
    float k33 = n33 - lam;

    // Symmetric adjugate of K (= c * q q^T).
    float a00 = k11*(k22*k33 - k23*k23) - k12*(k12*k33 - k13*k23) + k13*(k12*k23 - k13*k22);
    float a11 = k00*(k22*k33 - k23*k23) - k02*(k02*k33 - k03*k23) + k03*(k02*k23 - k03*k22);
    float a22 = k00*(k11*k33 - k13*k13) - k01*(k01*k33 - k03*k13) + k03*(k01*k13 - k03*k11);
    float a33 = k00*(k11*k22 - k12*k12) - k01*(k01*k22 - k02*k12) + k02*(k01*k12 - k02*k11);
    float a01 = -(k01*(k22*k33 - k23*k23) - k12*(k02*k33 - k03*k23) + k13*(k02*k23 - k03*k22));
    float a02 =   k01*(k12*k33 - k23*k13) - k11*(k02*k33 - k23*k03) + k13*(k02*k13 - k12*k03);
    float a03 = -(k01*(k12*k23 - k22*k13) - k11*(k02*k23 - k22*k03) + k12*(k02*k13 - k12*k03));
    float a12 = -(k00*(k12*k33 - k23*k13) - k01*(k02*k33 - k23*k03) + k03*(k02*k13 - k12*k03));
    float a13 =   k00*(k12*k23 - k22*k13) - k01*(k02*k23 - k22*k03) + k02*(k02*k13 - k12*k03);
    float a23 = -(k00*(k11*k23 - k12*k13) - k01*(k01*k23 - k12*k03) + k02*(k01*k13 - k11*k03));

    float q0, q1, q2, q3;
    float d0 = fabsf(a00), d1 = fabsf(a11), d2 = fabsf(a22), d3 = fabsf(a33);
    if (d0 >= d1 && d0 >= d2 && d0 >= d3) {
        q0 = a00; q1 = a01; q2 = a02; q3 = a03;
    } else if (d1 >= d2 && d1 >= d3) {
        q0 = a01; q1 = a11; q2 = a12; q3 = a13;
    } else if (d2 >= d3) {
        q0 = a02; q1 = a12; q2 = a22; q3 = a23;
    } else {
        q0 = a03; q1 = a13; q2 = a23; q3 = a33;
    }
    float nq = rsqrtf(q0*q0 + q1*q1 + q2*q2 + q3*q3 + 1e-30f);
    q0 *= nq; q1 *= nq; q2 *= nq; q3 *= nq;

    float xx = q1 * q1, yy = q2 * q2, zz = q3 * q3;
    float xy = q1 * q2, xz = q1 * q3, yz = q2 * q3;
    float wx = q0 * q1, wy = q0 * q2, wz = q0 * q3;

    float R00 = 1.0f - 2.0f * (yy + zz);
    float R01 = 2.0f * (xy - wz);
    float R02 = 2.0f * (xz + wy);
    float R10 = 2.0f * (xy + wz);
    float R11 = 1.0f - 2.0f * (xx + zz);
    float R12 = 2.0f * (yz - wx);
    float R20 = 2.0f * (xz - wy);
    float R21 = 2.0f * (yz + wx);
    float R22 = 1.0f - 2.0f * (xx + yy);

    float tx = Qb0 - (R00 * Pb0 + R01 * Pb1 + R02 * Pb2);
    float ty = Qb1 - (R10 * Pb0 + R11 * Pb1 + R12 * Pb2);
    float tz = Qb2 - (R20 * Pb0 + R21 * Pb1 + R22 * Pb2);

    const int grp_out = b * J_N + tid;
    float* oR = out + (size_t)grp_out * 9;
    oR[0] = R00; oR[1] = R01; oR[2] = R02;
    oR[3] = R10; oR[4] = R11; oR[5] = R12;
    oR[6] = R20; oR[7] = R21; oR[8] = R22;

    float* oT = out + (size_t)B_N * J_N * 9 + (size_t)grp_out * 3;
    oT[0] = tx; oT[1] = ty; oT[2] = tz;
}

extern "C" void kernel_launch(void* const* d_in, const int* in_sizes, int n_in,
                              void* d_out, int out_size)
{
    const float* points = (const float*)d_in[0];
    const float* weight = (const float*)d_in[1];
    const float* offset = (const float*)d_in[2];
    float* out = (float*)d_out;

    svd_solver_kernel<<<B_N, 96>>>(points, weight, offset, out);
}

// round 13
// speedup vs baseline: 1.8889x; 1.0875x over previous
#include <cuda_runtime.h>
#include <cuda_bf16.h>
#include <cstdint>

// SVD_Solver: batched weighted Kabsch.
// points (B,M,3) f32, weight (B,M,J) f32, offset (B,M,J,3) f32.
// out = [R (B,J,3,3) ; t (B,J,3)], f32.
//
// R13: (a) weight staged via cp.async with its quarter (contiguous 1536B)
// -> compute loop is pure smem+FMA, no in-loop LDG; (b) hybrid solve:
// QCP (Newton on quartic + adjugate eigenvector) with ill-conditioning
// detector falling back to 16x matrix-squaring for tiny-eigengap lanes.

#define B_N 4096
#define M_N 64
#define J_N 24

#define O_QTR (16 * J_N * 3)        // 1152 floats per quarter (offset)
#define W_QTR (16 * J_N)            // 384 floats per quarter (weight)
#define SLOT_FLOATS (O_QTR + W_QTR) // 1536 floats = 6144 B per slot
#define Q_FLOATS (M_N * 3)          // 192
#define SUM_STRIDE 23               // 22 sums + pad, gcd(23,32)=1

__device__ __forceinline__ void cp_async16(uint32_t smem_addr, const void* gptr) {
    asm volatile("cp.async.cg.shared.global [%0], [%1], 16;\n"
                 :: "r"(smem_addr), "l"(gptr));
}
__device__ __forceinline__ void cp_commit() {
    asm volatile("cp.async.commit_group;\n");
}
template <int N>
__device__ __forceinline__ void cp_wait() {
    asm volatile("cp.async.wait_group %0;\n" :: "n"(N));
}

__global__ void __launch_bounds__(96, 14)
svd_solver_kernel(const float* __restrict__ points,
                  const float* __restrict__ weight,
                  const float* __restrict__ offset,
                  float* __restrict__ out)
{
    __shared__ __align__(16) float smo[2 * SLOT_FLOATS];  // offset+weight, 2 slots
    __shared__ __align__(16) float smq[Q_FLOATS];
    __shared__ float sums[J_N * SUM_STRIDE];

    const int tid = threadIdx.x;
    const int b = blockIdx.x;

    const float* go = offset + (size_t)b * (M_N * J_N * 3);
    const float* gw = weight + (size_t)b * (M_N * J_N);
    const float* gq = points + (size_t)b * Q_FLOATS;

    const uint32_t so = (uint32_t)__cvta_generic_to_shared(smo);
    const uint32_t sq = (uint32_t)__cvta_generic_to_shared(smq);

    // Quarter qi -> slot: offset (3 float4/thr) + weight (1 float4/thr).
    auto issue_q = [&](int qi, int slot) {
        const float* srco = go + qi * O_QTR;
        const float* srcw = gw + qi * W_QTR;
        const uint32_t dsto = so + slot * (SLOT_FLOATS * 4);
        const uint32_t dstw = dsto + O_QTR * 4;
#pragma unroll
        for (int k = 0; k < 3; ++k) {
            int idx = k * 96 + tid;
            cp_async16(dsto + idx * 16, srco + idx * 4);
        }
        cp_async16(dstw + tid * 16, srcw + tid * 4);   // 96 float4 = 384 floats
    };

    issue_q(0, 0);
    if (tid < Q_FLOATS / 4)
        cp_async16(sq + tid * 16, gq + tid * 4);
    cp_commit();
    issue_q(1, 1);
    cp_commit();

    const int j = tid >> 2;
    const int sub = tid & 3;

    float sw = 0.f;
    float sP0 = 0.f, sP1 = 0.f, sP2 = 0.f;
    float sQ0 = 0.f, sQ1 = 0.f, sQ2 = 0.f;
    float wP0 = 0.f, wP1 = 0.f, wP2 = 0.f;
    float wQ0 = 0.f, wQ1 = 0.f, wQ2 = 0.f;
    float s00 = 0.f, s01 = 0.f, s02 = 0.f;
    float s10 = 0.f, s11 = 0.f, s12 = 0.f;
    float s20 = 0.f, s21 = 0.f, s22 = 0.f;

#pragma unroll 1
    for (int q = 0; q < 4; ++q) {
        if (q < 3) cp_wait<1>(); else cp_wait<0>();
        __syncthreads();

        const int mbase = q * 16;
        const float* ob = smo + (q & 1) * SLOT_FLOATS;
        const float* wb = ob + O_QTR;

#pragma unroll
        for (int ml = 0; ml < 4; ++ml) {
            const int m_local = ml * 4 + sub;
            float w = wb[m_local * J_N + j];              // conflict-free LDS
            const float* po = ob + (m_local * J_N + j) * 3;
            float p0 = po[0], p1 = po[1], p2 = po[2];
            const float* pq = smq + (mbase + m_local) * 3;
            float q0 = pq[0], q1 = pq[1], q2 = pq[2];

            sw += w;
            sP0 += p0; sP1 += p1; sP2 += p2;
            sQ0 += q0; sQ1 += q1; sQ2 += q2;
            wP0 = fmaf(w, p0, wP0); wP1 = fmaf(w, p1, wP1); wP2 = fmaf(w, p2, wP2);
            wQ0 = fmaf(w, q0, wQ0); wQ1 = fmaf(w, q1, wQ1); wQ2 = fmaf(w, q2, wQ2);
            s00 = fmaf(p0, q0, s00); s01 = fmaf(p0, q1, s01); s02 = fmaf(p0, q2, s02);
            s10 = fmaf(p1, q0, s10); s11 = fmaf(p1, q1, s11); s12 = fmaf(p1, q2, s12);
            s20 = fmaf(p2, q0, s20); s21 = fmaf(p2, q1, s21); s22 = fmaf(p2, q2, s22);
        }
        __syncthreads();

        if (q + 2 < 4) {
            issue_q(q + 2, q & 1);
            cp_commit();
        }
    }

#pragma unroll
    for (int d = 1; d < 4; d <<= 1) {
        sw  += __shfl_xor_sync(0xffffffffu, sw,  d);
        sP0 += __shfl_xor_sync(0xffffffffu, sP0, d);
        sP1 += __shfl_xor_sync(0xffffffffu, sP1, d);
        sP2 += __shfl_xor_sync(0xffffffffu, sP2, d);
        sQ0 += __shfl_xor_sync(0xffffffffu, sQ0, d);
        sQ1 += __shfl_xor_sync(0xffffffffu, sQ1, d);
        sQ2 += __shfl_xor_sync(0xffffffffu, sQ2, d);
        wP0 += __shfl_xor_sync(0xffffffffu, wP0, d);
        wP1 += __shfl_xor_sync(0xffffffffu, wP1, d);
        wP2 += __shfl_xor_sync(0xffffffffu, wP2, d);
        wQ0 += __shfl_xor_sync(0xffffffffu, wQ0, d);
        wQ1 += __shfl_xor_sync(0xffffffffu, wQ1, d);
        wQ2 += __shfl_xor_sync(0xffffffffu, wQ2, d);
        s00 += __shfl_xor_sync(0xffffffffu, s00, d);
        s01 += __shfl_xor_sync(0xffffffffu, s01, d);
        s02 += __shfl_xor_sync(0xffffffffu, s02, d);
        s10 += __shfl_xor_sync(0xffffffffu, s10, d);
        s11 += __shfl_xor_sync(0xffffffffu, s11, d);
        s12 += __shfl_xor_sync(0xffffffffu, s12, d);
        s20 += __shfl_xor_sync(0xffffffffu, s20, d);
        s21 += __shfl_xor_sync(0xffffffffu, s21, d);
        s22 += __shfl_xor_sync(0xffffffffu, s22, d);
    }
    if (sub == 0) {
        float* s = sums + j * SUM_STRIDE;
        s[0]  = sw;
        s[1]  = sP0; s[2]  = sP1; s[3]  = sP2;
        s[4]  = sQ0; s[5]  = sQ1; s[6]  = sQ2;
        s[7]  = wP0; s[8]  = wP1; s[9]  = wP2;
        s[10] = wQ0; s[11] = wQ1; s[12] = wQ2;
        s[13] = s00; s[14] = s01; s[15] = s02;
        s[16] = s10; s[17] = s11; s[18] = s12;
        s[19] = s20; s[20] = s21; s[21] = s22;
    }
    __syncthreads();

    if (tid >= J_N) return;

    // ---- Solve: warp 0, one j per lane; QCP + ill-conditioning fallback ----
    const float* s = sums + tid * SUM_STRIDE;
    float Tsw = s[0];
    float TsP0 = s[1],  TsP1 = s[2],  TsP2 = s[3];
    float TsQ0 = s[4],  TsQ1 = s[5],  TsQ2 = s[6];
    float TwP0 = s[7],  TwP1 = s[8],  TwP2 = s[9];
    float TwQ0 = s[10], TwQ1 = s[11], TwQ2 = s[12];
    float t00 = s[13], t01 = s[14], t02 = s[15];
    float t10 = s[16], t11 = s[17], t12 = s[18];
    float t20 = s[19], t21 = s[20], t22 = s[21];

    float inv = 1.0f / Tsw;
    float Pb0 = TwP0 * inv, Pb1 = TwP1 * inv, Pb2 = TwP2 * inv;
    float Qb0 = TwQ0 * inv, Qb1 = TwQ1 * inv, Qb2 = TwQ2 * inv;

    float g0 = TsP0 - (float)M_N * Pb0;
    float g1 = TsP1 - (float)M_N * Pb1;
    float g2 = TsP2 - (float)M_N * Pb2;

    float Sxx = t00 - Pb0 * TsQ0 - g0 * Qb0;
    float Sxy = t01 - Pb0 * TsQ1 - g0 * Qb1;
    float Sxz = t02 - Pb0 * TsQ2 - g0 * Qb2;
    float Syx = t10 - Pb1 * TsQ0 - g1 * Qb0;
    float Syy = t11 - Pb1 * TsQ1 - g1 * Qb1;
    float Syz = t12 - Pb1 * TsQ2 - g1 * Qb2;
    float Szx = t20 - Pb2 * TsQ0 - g2 * Qb0;
    float Szy = t21 - Pb2 * TsQ1 - g2 * Qb1;
    float Szz = t22 - Pb2 * TsQ2 - g2 * Qb2;

    // Horn's N (shared by both paths)
    float n00 = Sxx + Syy + Szz;
    float n01 = Syz - Szy;
    float n02 = Szx - Sxz;
    float n03 = Sxy - Syx;
    float n11 = Sxx - Syy - Szz;
    float n12 = Sxy + Syx;
    float n13 = Szx + Sxz;
    float n22 = -Sxx + Syy - Szz;
    float n23 = Syz + Szy;
    float n33 = -Sxx - Syy + Szz;

    // --- QCP fast path ---
    float P2 = Sxx*Sxx + Sxy*Sxy + Sxz*Sxz + Syx*Syx + Syy*Syy + Syz*Syz
             + Szx*Szx + Szy*Szy + Szz*Szz;
    float C2 = -2.0f * P2;
    float detS = Sxx * (Syy * Szz - Syz * Szy)
               - Sxy * (Syx * Szz - Syz * Szx)
               + Sxz * (Syx * Szy - Syy * Szx);
    float C1 = -8.0f * detS;
    float M00 = Sxx*Sxx + Syx*Syx + Szx*Szx;
    float M11 = Sxy*Sxy + Syy*Syy + Szy*Szy;
    float M22 = Sxz*Sxz + Syz*Syz + Szz*Szz;
    float M01 = Sxx*Sxy + Syx*Syy + Szx*Szy;
    float M02 = Sxx*Sxz + Syx*Syz + Szx*Szz;
    float M12 = Sxy*Sxz + Syy*Syz + Szy*Szz;
    float trM2 = M00*M00 + M11*M11 + M22*M22
               + 2.0f * (M01*M01 + M02*M02 + M12*M12);
    float pp  = P2 * P2;
    float ppe = fmaf(P2, P2, -pp);
    float C0 = (2.0f * trM2 - pp) - ppe;

    float lam = sqrtf(3.0f * P2);
#pragma unroll
    for (int it = 0; it < 10; ++it) {
        float f  = fmaf(fmaf(fmaf(lam, lam, C2), lam, C1), lam, C0);
        float fp = fmaf(fmaf(4.0f * lam, lam, 2.0f * C2), lam, C1);
        lam -= f / (fp + 1e-20f);
    }

    float k00 = n00 - lam, k01 = n01, k02 = n02, k03 = n03;
    float k11 = n11 - lam, k12 = n12, k13 = n13;
    float k22 = n22 - lam, k23 = n23;
    float k33 = n33 - lam;

    float a00 = k11*(k22*k33 - k23*k23) - k12*(k12*k33 - k13*k23) + k13*(k12*k23 - k13*k22);
    float a11 = k00*(k22*k33 - k23*k23) - k02*(k02*k33 - k03*k23) + k03*(k02*k23 - k03*k22);
    float a22 = k00*(k11*k33 - k13*k13) - k01*(k01*k33 - k03*k13) + k03*(k01*k13 - k03*k11);
    float a33 = k00*(k11*k22 - k12*k12) - k01*(k01*k22 - k02*k12) + k02*(k01*k12 - k02*k11);
    float a01 = -(k01*(k22*k33 - k23*k23) - k12*(k02*k33 - k03*k23) + k13*(k02*k23 - k03*k22));
    float a02 =   k01*(k12*k33 - k23*k13) - k11*(k02*k33 - k23*k03) + k13*(k02*k13 - k12*k03);
    float a03 = -(k01*(k12*k23 - k22*k13) - k11*(k02*k23 - k22*k03) + k12*(k02*k13 - k12*k03));
    float a12 = -(k00*(k12*k33 - k23*k13) - k01*(k02*k33 - k23*k03) + k03*(k02*k13 - k12*k03));
    float a13 =   k00*(k12*k23 - k22*k13) - k01*(k02*k23 - k22*k03) + k02*(k02*k13 - k12*k03);
    float a23 = -(k00*(k11*k23 - k12*k13) - k01*(k01*k23 - k12*k03) + k02*(k01*k13 - k11*k03));

    float q0, q1, q2, q3;
    float d0 = fabsf(a00), d1 = fabsf(a11), d2 = fabsf(a22), d3 = fabsf(a33);
    float dmax = fmaxf(fmaxf(d0, d1), fmaxf(d2, d3));

    if (dmax > 3e-3f * lam * lam * lam) {
        // Well-conditioned: take adjugate column with largest diagonal.
        if (d0 >= d1 && d0 >= d2 && d0 >= d3) {
            q0 = a00; q1 = a01; q2 = a02; q3 = a03;
        } else if (d1 >= d2 && d1 >= d3) {
            q0 = a01; q1 = a11; q2 = a12; q3 = a13;
        } else if (d2 >= d3) {
            q0 = a02; q1 = a12; q2 = a22; q3 = a23;
        } else {
            q0 = a03; q1 = a13; q2 = a23; q3 = a33;
        }
    } else {
        // Fallback: 16x shifted matrix squaring (robust to tiny eigengap).
        float f2 = n00*n00 + n11*n11 + n22*n22 + n33*n33 +
                   2.0f * (n01*n01 + n02*n02 + n03*n03 +
                           n12*n12 + n13*n13 + n23*n23);
        float sh = sqrtf(f2) + 1e-30f;
        float b00 = n00 + sh, b01 = n01, b02 = n02, b03 = n03;
        float b11 = n11 + sh, b12 = n12, b13 = n13;
        float b22 = n22 + sh, b23 = n23;
        float b33 = n33 + sh;
#pragma unroll 1
        for (int it = 0; it < 16; ++it) {
            float c00 = b00*b00 + b01*b01 + b02*b02 + b03*b03;
            float c01 = b00*b01 + b01*b11 + b02*b12 + b03*b13;
            float c02 = b00*b02 + b01*b12 + b02*b22 + b03*b23;
            float c03 = b00*b03 + b01*b13 + b02*b23 + b03*b33;
            float c11 = b01*b01 + b11*b11 + b12*b12 + b13*b13;
            float c12 = b01*b02 + b11*b12 + b12*b22 + b13*b23;
            float c13 = b01*b03 + b11*b13 + b12*b23 + b13*b33;
            float c22 = b02*b02 + b12*b12 + b22*b22 + b23*b23;
            float c23 = b02*b03 + b12*b13 + b22*b23 + b23*b33;
            float c33 = b03*b03 + b13*b13 + b23*b23 + b33*b33;
            float tr = c00 + c11 + c22 + c33;
            float sc = __frcp_rn(tr);
            b00 = c00*sc; b01 = c01*sc; b02 = c02*sc; b03 = c03*sc;
            b11 = c11*sc; b12 = c12*sc; b13 = c13*sc;
            b22 = c22*sc; b23 = c23*sc;
            b33 = c33*sc;
        }
        if (b00 >= b11 && b00 >= b22 && b00 >= b33) {
            q0 = b00; q1 = b01; q2 = b02; q3 = b03;
        } else if (b11 >= b22 && b11 >= b33) {
            q0 = b01; q1 = b11; q2 = b12; q3 = b13;
        } else if (b22 >= b33) {
            q0 = b02; q1 = b12; q2 = b22; q3 = b23;
        } else {
            q0 = b03; q1 = b13; q2 = b23; q3 = b33;
        }
    }

    float nq = rsqrtf(q0*q0 + q1*q1 + q2*q2 + q3*q3 + 1e-30f);
    q0 *= nq; q1 *= nq; q2 *= nq; q3 *= nq;

    float xx = q1 * q1, yy = q2 * q2, zz = q3 * q3;
    float xy = q1 * q2, xz = q1 * q3, yz = q2 * q3;
    float wx = q0 * q1, wy = q0 * q2, wz = q0 * q3;

    float R00 = 1.0f - 2.0f * (yy + zz);
    float R01 = 2.0f * (xy - wz);
    float R02 = 2.0f * (xz + wy);
    float R10 = 2.0f * (xy + wz);
    float R11 = 1.0f - 2.0f * (xx + zz);
    float R12 = 2.0f * (yz - wx);
    float R20 = 2.0f * (xz - wy);
    float R21 = 2.0f * (yz + wx);
    float R22 = 1.0f - 2.0f * (xx + yy);

    float tx = Qb0 - (R00 * Pb0 + R01 * Pb1 + R02 * Pb2);
    float ty = Qb1 - (R10 * Pb0 + R11 * Pb1 + R12 * Pb2);
    float tz = Qb2 - (R20 * Pb0 + R21 * Pb1 + R22 * Pb2);

    const int grp_out = b * J_N + tid;
    float* oR = out + (size_t)grp_out * 9;
    oR[0] = R00; oR[1] = R01; oR[2] = R02;
    oR[3] = R10; oR[4] = R11; oR[5] = R12;
    oR[6] = R20; oR[7] = R21; oR[8] = R22;

    float* oT = out + (size_t)B_N * J_N * 9 + (size_t)grp_out * 3;
    oT[0] = tx; oT[1] = ty; oT[2] = tz;
}

extern "C" void kernel_launch(void* const* d_in, const int* in_sizes, int n_in,
                              void* d_out, int out_size)
{
    const float* points = (const float*)d_in[0];
    const float* weight = (const float*)d_in[1];
    const float* offset = (const float*)d_in[2];
    float* out = (float*)d_out;

    svd_solver_kernel<<<B_N, 96>>>(points, weight, offset, out);
}